// round 13
// baseline (speedup 1.0000x reference)
#include <cuda_runtime.h>
#include <cstdint>

#define BB   2
#define SS   2048
#define DD   1024
#define HQ   16
#define HKV  8
#define HD   128
#define NTOK (BB*SS)
#define NBH  (BB*HQ)

// ---------------- device scratch ------------------------------------------
__device__ float g_qlin[(size_t)NTOK * HQ  * HD];
__device__ float g_klin[(size_t)NTOK * HKV * HD];
__device__ float g_vlin[(size_t)NTOK * HKV * HD];
__device__ float g_q  [(size_t)BB * HQ  * SS * HD];
__device__ float g_k  [(size_t)BB * HKV * SS * HD];
__device__ float g_vt [(size_t)BB * HKV * HD * SS];   // V^T [b][kv][d][s]
__device__ float g_o  [(size_t)NTOK * HQ * HD];
__device__ float g_wfall[(size_t)BB * HQ * SS * SS];
__device__ float g_hst[(size_t)NTOK * DD];
__device__ float g_wqt[(size_t)HQ  * HD * DD];
__device__ float g_wkt[(size_t)HKV * HD * DD];
__device__ float g_wvt[(size_t)HKV * HD * DD];
__device__ float g_wot[(size_t)DD * HQ * HD];

// ---------------------------------------------------------------------------
__device__ __forceinline__ uint32_t f2tf32(float x) {
    uint32_t r; asm("cvt.rna.tf32.f32 %0, %1;" : "=r"(r) : "f"(x)); return r;
}
__device__ __forceinline__ float rtf(float x) { return __uint_as_float(f2tf32(x)); }
__device__ __forceinline__ void mma8(float* d, const uint32_t* a, const uint32_t* b) {
    asm volatile("mma.sync.aligned.m16n8k8.row.col.f32.tf32.tf32.f32 "
        "{%0,%1,%2,%3}, {%4,%5,%6,%7}, {%8,%9}, {%0,%1,%2,%3};"
        : "+f"(d[0]), "+f"(d[1]), "+f"(d[2]), "+f"(d[3])
        : "r"(a[0]), "r"(a[1]), "r"(a[2]), "r"(a[3]), "r"(b[0]), "r"(b[1]));
}

// Dynamic smem word layout (2 stages x 4 k8-groups):
//  A(s,kt,mf):  ((s*4+kt)*8  + mf)*128   + lane*4 + reg   (8192 words)
//  B(s,kt,nf):  8192 + ((s*4+kt)*16 + nf)*64 + lane*2 + reg (8192 words)
#define GEMM_SMEM_BYTES 65536
__device__ __forceinline__ int Aoff(int s, int kt, int mf) {
    return ((s * 4 + kt) * 8 + mf) * 128;
}
__device__ __forceinline__ int Boff(int s, int kt, int nf) {
    return 8192 + ((s * 4 + kt) * 16 + nf) * 64;
}

// 128x128 block tile, 128 threads (4 warps 2x2), warp tile 64x64, NT only.
// Inputs pre-rounded to tf32. Double-buffered K32 stages, ONE barrier per k32.
template<int RND>
__device__ __forceinline__ void gemm_core(
    const float* __restrict__ A, const float* __restrict__ B,
    float* __restrict__ C, int lda, int ldb, int ldc,
    int kIters, float alpha)          // kIters = K / 32
{
    extern __shared__ uint32_t smw[];

    const int t = threadIdx.x;
    const int lane = t & 31;
    const int warp = t >> 5;
    const int wm = warp >> 1;
    const int wn = warp & 1;

    float acc[4][8][4];
#pragma unroll
    for (int i = 0; i < 4; i++)
#pragma unroll
        for (int j = 0; j < 8; j++)
#pragma unroll
            for (int r = 0; r < 4; r++) acc[i][j][r] = 0.f;

    // A producer: pair p = t>>1 -> rows (mfA*16+gA, +8); ktA = t&1 -> k16 half
    const int pA = t >> 1, ktA = t & 1;
    const int mfA = pA >> 3, gA = pA & 7;
    const float* ApA = A + (size_t)(mfA * 16 + gA) * lda + ktA * 16;
    const float* ApB = ApA + (size_t)8 * lda;
    // B producer: row n = t, all 32 k
    const float* BpN = B + (size_t)t * ldb;
    const int nfB = t >> 3, lbB = (t & 7) * 4;

    float ax[32];   // [h*16 + {0..3: row r k0..3, 4..7: r k4..7, 8..11: r+8 k0..3, 12..15: r+8 k4..7}]
    float bz[32];   // [kt*8 + 0..7] = row n, k kt*8..kt*8+7
    {
        float4 v;
#pragma unroll
        for (int h = 0; h < 2; ++h) {
            v = *(const float4*)(ApA + h * 8);     ax[h*16+0]=v.x; ax[h*16+1]=v.y; ax[h*16+2]=v.z; ax[h*16+3]=v.w;
            v = *(const float4*)(ApA + h * 8 + 4); ax[h*16+4]=v.x; ax[h*16+5]=v.y; ax[h*16+6]=v.z; ax[h*16+7]=v.w;
            v = *(const float4*)(ApB + h * 8);     ax[h*16+8]=v.x; ax[h*16+9]=v.y; ax[h*16+10]=v.z; ax[h*16+11]=v.w;
            v = *(const float4*)(ApB + h * 8 + 4); ax[h*16+12]=v.x; ax[h*16+13]=v.y; ax[h*16+14]=v.z; ax[h*16+15]=v.w;
        }
#pragma unroll
        for (int w8 = 0; w8 < 8; ++w8) {
            v = *(const float4*)(BpN + w8 * 4);
            bz[w8*4+0]=v.x; bz[w8*4+1]=v.y; bz[w8*4+2]=v.z; bz[w8*4+3]=v.w;
        }
    }

    for (int it = 0; it < kIters; ++it) {
        const int st = it & 1;
        // A: 2 k8-groups x 4 STS.128 (fragment-ready)
#pragma unroll
        for (int h = 0; h < 2; ++h) {
            uint4* dst = (uint4*)&smw[Aoff(st, ktA * 2 + h, mfA) + gA * 16];
            const float* gx = ax + h * 16;
#pragma unroll
            for (int q = 0; q < 4; ++q)
                dst[q] = make_uint4(__float_as_uint(gx[q]),
                                    __float_as_uint(gx[8 + q]),
                                    __float_as_uint(gx[4 + q]),
                                    __float_as_uint(gx[12 + q]));
        }
        // B: 4 k8-groups x 2 STS.128
#pragma unroll
        for (int kt = 0; kt < 4; ++kt) {
            uint4* dst = (uint4*)&smw[Boff(st, kt, nfB) + lbB * 2];
            const float* z = bz + kt * 8;
            dst[0] = make_uint4(__float_as_uint(z[0]), __float_as_uint(z[4]),
                                __float_as_uint(z[1]), __float_as_uint(z[5]));
            dst[1] = make_uint4(__float_as_uint(z[2]), __float_as_uint(z[6]),
                                __float_as_uint(z[3]), __float_as_uint(z[7]));
        }
        __syncthreads();
        // preload next k32
        if (it + 1 < kIters) {
            const int k0 = (it + 1) * 32;
            float4 v;
#pragma unroll
            for (int h = 0; h < 2; ++h) {
                v = *(const float4*)(ApA + k0 + h * 8);     ax[h*16+0]=v.x; ax[h*16+1]=v.y; ax[h*16+2]=v.z; ax[h*16+3]=v.w;
                v = *(const float4*)(ApA + k0 + h * 8 + 4); ax[h*16+4]=v.x; ax[h*16+5]=v.y; ax[h*16+6]=v.z; ax[h*16+7]=v.w;
                v = *(const float4*)(ApB + k0 + h * 8);     ax[h*16+8]=v.x; ax[h*16+9]=v.y; ax[h*16+10]=v.z; ax[h*16+11]=v.w;
                v = *(const float4*)(ApB + k0 + h * 8 + 4); ax[h*16+12]=v.x; ax[h*16+13]=v.y; ax[h*16+14]=v.z; ax[h*16+15]=v.w;
            }
#pragma unroll
            for (int w8 = 0; w8 < 8; ++w8) {
                v = *(const float4*)(BpN + k0 + w8 * 4);
                bz[w8*4+0]=v.x; bz[w8*4+1]=v.y; bz[w8*4+2]=v.z; bz[w8*4+3]=v.w;
            }
        }
        // compute 4 k8 sub-tiles
#pragma unroll
        for (int kt = 0; kt < 4; kt++) {
            uint32_t ah[4][4];
#pragma unroll
            for (int i = 0; i < 4; i++) {
                uint4 h = *(const uint4*)&smw[Aoff(st, kt, wm * 4 + i) + lane * 4];
                ah[i][0] = h.x; ah[i][1] = h.y; ah[i][2] = h.z; ah[i][3] = h.w;
            }
            uint32_t bh[8][2];
#pragma unroll
            for (int j = 0; j < 8; j++) {
                uint2 h = *(const uint2*)&smw[Boff(st, kt, wn * 8 + j) + lane * 2];
                bh[j][0] = h.x; bh[j][1] = h.y;
            }
#pragma unroll
            for (int i = 0; i < 4; i++)
#pragma unroll
                for (int j = 0; j < 8; j++)
                    mma8(acc[i][j], ah[i], bh[j]);
        }
    }
    const int g = lane >> 2, q = lane & 3;
#pragma unroll
    for (int i = 0; i < 4; i++) {
        int r0 = wm * 64 + i * 16 + g;
#pragma unroll
        for (int j = 0; j < 8; j++) {
            int col = wn * 64 + j * 8 + q * 2;
            float o0 = acc[i][j][0] * alpha, o1 = acc[i][j][1] * alpha;
            float o2 = acc[i][j][2] * alpha, o3 = acc[i][j][3] * alpha;
            if (RND) { o0 = rtf(o0); o1 = rtf(o1); o2 = rtf(o2); o3 = rtf(o3); }
            *(float2*)&C[(size_t)r0 * ldc + col]       = make_float2(o0, o1);
            *(float2*)&C[(size_t)(r0 + 8) * ldc + col] = make_float2(o2, o3);
        }
    }
}

// ---------------- wrappers -------------------------------------------------
__global__ void __launch_bounds__(128, 2) qkv_mma(
    const float* __restrict__ hs,
    const float* __restrict__ wq, const float* __restrict__ wk,
    const float* __restrict__ wv,
    float* __restrict__ qlin, float* __restrict__ klin, float* __restrict__ vlin)
{
    const int bx = blockIdx.x;
    int z, xb;
    if (bx < 16)      { z = 0; xb = bx; }
    else if (bx < 24) { z = 1; xb = bx - 16; }
    else              { z = 2; xb = bx - 24; }
    const int nblk = (z == 0) ? 16 : 8;
    const float* B = (z == 0) ? wq : ((z == 1) ? wk : wv);
    float* C       = (z == 0) ? qlin : ((z == 1) ? klin : vlin);
    const int ldc  = nblk * 128;
    gemm_core<0>(hs + (size_t)blockIdx.y * 128 * DD,
                 B  + (size_t)xb * 128 * DD,
                 C  + (size_t)blockIdx.y * 128 * ldc + xb * 128,
                 DD, DD, ldc, DD / 32, 1.f);
}

__global__ void __launch_bounds__(128, 2) wo_mma(
    const float* __restrict__ A, const float* __restrict__ B,
    float* __restrict__ C)
{
    gemm_core<0>(A + (size_t)blockIdx.y * 128 * (HQ * HD),
                 B + (size_t)blockIdx.x * 128 * (HQ * HD),
                 C + (size_t)blockIdx.y * 128 * DD + blockIdx.x * 128,
                 HQ * HD, HQ * HD, DD, (HQ * HD) / 32, 1.f);
}

// scores: compact triangular grid, 136 tiles per (b,h)
__global__ void __launch_bounds__(128, 2) scores_mma(
    const float* __restrict__ Q, const float* __restrict__ Kk,
    float* __restrict__ W)
{
    const int u = blockIdx.x, z = blockIdx.z;
    int by = (int)((sqrtf(8.f * (float)u + 1.f) - 1.f) * 0.5f);
    while ((by + 1) * (by + 2) / 2 <= u) by++;
    while (by * (by + 1) / 2 > u) by--;
    const int bx = u - by * (by + 1) / 2;
    const int kvz = (z >> 4) * HKV + ((z & 15) >> 1);
    gemm_core<0>(Q  + ((size_t)z   * SS + by * 128) * HD,
                 Kk + ((size_t)kvz * SS + bx * 128) * HD,
                 W + (size_t)z * SS * SS + (size_t)by * 128 * SS + bx * 128,
                 HD, HD, SS, HD / 32, 0.08838834764831845f);
}

// av: heaviest strips launch FIRST
__global__ void __launch_bounds__(128, 2) av_mma(
    const float* __restrict__ W, const float* __restrict__ Vt,
    float* __restrict__ O)
{
    const int by = 15 - blockIdx.y, z = blockIdx.z;
    const int kvz = (z >> 4) * HKV + ((z & 15) >> 1);
    gemm_core<1>(W  + (size_t)z * SS * SS + (size_t)by * 128 * SS,
                 Vt + (size_t)kvz * HD * SS,
                 O + (size_t)(z >> 4) * SS * (HQ * HD)
                   + (size_t)by * 128 * (HQ * HD) + (z & 15) * HD,
                 SS, SS, HQ * HD, (by + 1) * 4, 1.f);
}

// ============== tf32 pre-rounding ==========================================
__global__ void round_kernel(const float* __restrict__ src,
                             float* __restrict__ dst, int n4)
{
    int i = blockIdx.x * 256 + threadIdx.x;
    if (i >= n4) return;
    float4 v = ((const float4*)src)[i];
    v.x = rtf(v.x); v.y = rtf(v.y); v.z = rtf(v.z); v.w = rtf(v.w);
    ((float4*)dst)[i] = v;
}

// ======== RMSNorm + RoPE for Q/K. Grid (NTOK, 24), 128 threads =============
__global__ void rmsrope_kernel(const float* __restrict__ qlin,
                               const float* __restrict__ klin,
                               const float* __restrict__ cosb,
                               const float* __restrict__ sinb,
                               const float* __restrict__ qw,
                               const float* __restrict__ kw,
                               float* __restrict__ qout,
                               float* __restrict__ kout)
{
    const int token = blockIdx.x;
    const int y     = blockIdx.y;
    const int i     = threadIdx.x;
    const int b = token >> 11, s = token & (SS - 1);
    __shared__ float sh[128];
    __shared__ float red[4];

    float c  = cosb[(size_t)token * HD + i];
    float sn = sinb[(size_t)token * HD + i];
    float x, w;
    float* outp;
    if (y < HQ) {
        x = qlin[(size_t)token * (HQ * HD) + y * HD + i];
        w = qw[i];
        outp = qout + (((size_t)(b * HQ + y)) * SS + s) * HD;
    } else {
        int h = y - HQ;
        x = klin[(size_t)token * (HKV * HD) + h * HD + i];
        w = kw[i];
        outp = kout + (((size_t)(b * HKV + h)) * SS + s) * HD;
    }
    float ss = x * x;
#pragma unroll
    for (int off = 16; off; off >>= 1) ss += __shfl_xor_sync(0xffffffffu, ss, off);
    const int lane = i & 31, wd = i >> 5;
    if (lane == 0) red[wd] = ss;
    __syncthreads();
    ss = red[0] + red[1] + red[2] + red[3];
    float inv = rsqrtf(ss * (1.f / HD) + 1e-6f);
    float xn  = x * inv * w;
    sh[i] = xn;
    __syncthreads();
    float rot = (i < 64) ? -sh[i + 64] : sh[i - 64];
    outp[i] = rtf(xn * c + rot * sn);
}

// ======== V transpose: vlin [tok][kv*128] -> vt [b][kv][d][s] ==============
__global__ void vtrans_kernel(const float* __restrict__ vlin,
                              float* __restrict__ vt)
{
    __shared__ float tile[32][33];
    const int bkv = blockIdx.z;
    const int b = bkv >> 3, kv = bkv & 7;
    const int s0 = blockIdx.x * 32, d0 = blockIdx.y * 32;
    const int tx = threadIdx.x, ty = threadIdx.y;   // 32 x 8
#pragma unroll
    for (int r = 0; r < 32; r += 8) {
        int s = s0 + ty + r;
        tile[ty + r][tx] = vlin[((size_t)b * SS + s) * (HKV * HD) + kv * HD + d0 + tx];
    }
    __syncthreads();
#pragma unroll
    for (int r = 0; r < 32; r += 8) {
        int d = d0 + ty + r;
        vt[(((size_t)bkv) * HD + d) * SS + s0 + tx] = rtf(tile[tx][ty + r]);
    }
}

// ======= in-place causal softmax, float4 I/O, loads guarded by L ===========
__global__ void softmax_kernel(float* __restrict__ W)
{
    const size_t row = blockIdx.x;
    const int iq = (int)(row & (SS - 1));
    const int L = iq + 1;
    float4* p = (float4*)(W + row * SS);
    const int t = threadIdx.x;               // 256 threads, 2 f4 each
    __shared__ float red[8];

    float4 v[2];
#pragma unroll
    for (int r = 0; r < 2; ++r) {
        int e0 = (t + r * 256) * 4;
        v[r] = (e0 < L) ? p[t + r * 256] : make_float4(0.f, 0.f, 0.f, 0.f);
    }

    float m = -3.4e38f;
#pragma unroll
    for (int r = 0; r < 2; ++r) {
        int e0 = (t + r * 256) * 4;
        float* f = (float*)&v[r];
#pragma unroll
        for (int e = 0; e < 4; ++e) if (e0 + e < L) m = fmaxf(m, f[e]);
    }
#pragma unroll
    for (int off = 16; off; off >>= 1) m = fmaxf(m, __shfl_xor_sync(0xffffffffu, m, off));
    if ((t & 31) == 0) red[t >> 5] = m;
    __syncthreads();
    m = red[0];
#pragma unroll
    for (int wq = 1; wq < 8; wq++) m = fmaxf(m, red[wq]);
    __syncthreads();

    float ssum = 0.f;
#pragma unroll
    for (int r = 0; r < 2; ++r) {
        int e0 = (t + r * 256) * 4;
        float* f = (float*)&v[r];
#pragma unroll
        for (int e = 0; e < 4; ++e) {
            float ex = (e0 + e < L) ? __expf(f[e] - m) : 0.f;
            f[e] = ex;
            ssum += ex;
        }
    }
#pragma unroll
    for (int off = 16; off; off >>= 1) ssum += __shfl_xor_sync(0xffffffffu, ssum, off);
    if ((t & 31) == 0) red[t >> 5] = ssum;
    __syncthreads();
    ssum = red[0] + red[1] + red[2] + red[3] + red[4] + red[5] + red[6] + red[7];
    const float inv = 1.f / ssum;

#pragma unroll
    for (int r = 0; r < 2; ++r) {
        float* f = (float*)&v[r];
#pragma unroll
        for (int e = 0; e < 4; ++e) f[e] = rtf(f[e] * inv);
        p[t + r * 256] = v[r];
    }
}

// ============================== launch ======================================
extern "C" void kernel_launch(void* const* d_in, const int* in_sizes, int n_in,
                              void* d_out, int out_size)
{
    const float* hs   = (const float*)d_in[0];
    const float* cosb = (const float*)d_in[1];
    const float* sinb = (const float*)d_in[2];
    const float* Wq   = (const float*)d_in[4];
    const float* Wk   = (const float*)d_in[5];
    const float* Wv   = (const float*)d_in[6];
    const float* Wo   = (const float*)d_in[7];
    const float* qw   = (const float*)d_in[8];
    const float* kw   = (const float*)d_in[9];
    float* out = (float*)d_out;

    float *qlin, *klin, *vlin, *qr, *kr, *vt, *osc, *wfall;
    float *hst, *wqt, *wkt, *wvt, *wot;
    cudaGetSymbolAddress((void**)&qlin, g_qlin);
    cudaGetSymbolAddress((void**)&klin, g_klin);
    cudaGetSymbolAddress((void**)&vlin, g_vlin);
    cudaGetSymbolAddress((void**)&qr,   g_q);
    cudaGetSymbolAddress((void**)&kr,   g_k);
    cudaGetSymbolAddress((void**)&vt,   g_vt);
    cudaGetSymbolAddress((void**)&osc,  g_o);
    cudaGetSymbolAddress((void**)&wfall, g_wfall);
    cudaGetSymbolAddress((void**)&hst,  g_hst);
    cudaGetSymbolAddress((void**)&wqt,  g_wqt);
    cudaGetSymbolAddress((void**)&wkt,  g_wkt);
    cudaGetSymbolAddress((void**)&wvt,  g_wvt);
    cudaGetSymbolAddress((void**)&wot,  g_wot);

    // allow 64KB dynamic smem on the GEMM kernels (idempotent)
    cudaFuncSetAttribute(qkv_mma,    cudaFuncAttributeMaxDynamicSharedMemorySize, GEMM_SMEM_BYTES);
    cudaFuncSetAttribute(wo_mma,     cudaFuncAttributeMaxDynamicSharedMemorySize, GEMM_SMEM_BYTES);
    cudaFuncSetAttribute(scores_mma, cudaFuncAttributeMaxDynamicSharedMemorySize, GEMM_SMEM_BYTES);
    cudaFuncSetAttribute(av_mma,     cudaFuncAttributeMaxDynamicSharedMemorySize, GEMM_SMEM_BYTES);
    cudaFuncSetAttribute(qkv_mma,    cudaFuncAttributePreferredSharedMemoryCarveout, 100);
    cudaFuncSetAttribute(wo_mma,     cudaFuncAttributePreferredSharedMemoryCarveout, 100);
    cudaFuncSetAttribute(scores_mma, cudaFuncAttributePreferredSharedMemoryCarveout, 100);
    cudaFuncSetAttribute(av_mma,     cudaFuncAttributePreferredSharedMemoryCarveout, 100);

    const size_t OUT_ELEMS = (size_t)NTOK * DD;
    const size_t W_ELEMS   = (size_t)BB * HQ * SS * SS;
    float* wptr = ((size_t)out_size >= OUT_ELEMS + W_ELEMS) ? (out + OUT_ELEMS)
                                                            : wfall;

    // tf32 pre-rounding of raw GEMM inputs
    {
        int n;
        n = NTOK * DD / 4;        round_kernel<<<(n + 255) / 256, 256>>>(hs, hst, n);
        n = HQ * HD * DD / 4;     round_kernel<<<(n + 255) / 256, 256>>>(Wq, wqt, n);
        n = HKV * HD * DD / 4;    round_kernel<<<(n + 255) / 256, 256>>>(Wk, wkt, n);
        n = HKV * HD * DD / 4;    round_kernel<<<(n + 255) / 256, 256>>>(Wv, wvt, n);
        n = DD * HQ * HD / 4;     round_kernel<<<(n + 255) / 256, 256>>>(Wo, wot, n);
    }

    dim3 blk(128);
    // QKV projections (compact grid)
    qkv_mma<<<dim3(32, NTOK / 128), blk, GEMM_SMEM_BYTES>>>(hst, wqt, wkt, wvt,
                                                            qlin, klin, vlin);
    // RMSNorm + RoPE (Q,K)
    rmsrope_kernel<<<dim3(NTOK, HQ + HKV), 128>>>(qlin, klin, cosb, sinb,
                                                  qw, kw, qr, kr);
    // V transpose
    vtrans_kernel<<<dim3(SS / 32, HD / 32, BB * HKV), dim3(32, 8)>>>(vlin, vt);
    // scores (compact triangular grid)
    scores_mma<<<dim3(136, 1, NBH), blk, GEMM_SMEM_BYTES>>>(qr, kr, wptr);
    // in-place causal softmax
    softmax_kernel<<<(unsigned)(NBH * SS), 256>>>(wptr);
    // AV (causal K bound, heavy-first)
    av_mma<<<dim3(1, SS / 128, NBH), blk, GEMM_SMEM_BYTES>>>(wptr, vt, osc);
    // output projection
    wo_mma<<<dim3(DD / 128, NTOK / 128), blk, GEMM_SMEM_BYTES>>>(osc, wot, out);
}

// round 15
// speedup vs baseline: 1.1266x; 1.1266x over previous
#include <cuda_runtime.h>
#include <cstdint>

#define BB   2
#define SS   2048
#define DD   1024
#define HQ   16
#define HKV  8
#define HD   128
#define NTOK (BB*SS)
#define NBH  (BB*HQ)

// ---------------- device scratch ------------------------------------------
__device__ float g_qlin[(size_t)NTOK * HQ  * HD];
__device__ float g_klin[(size_t)NTOK * HKV * HD];
__device__ float g_vlin[(size_t)NTOK * HKV * HD];
__device__ float g_q  [(size_t)BB * HQ  * SS * HD];
__device__ float g_k  [(size_t)BB * HKV * SS * HD];
__device__ float g_vt [(size_t)BB * HKV * HD * SS];   // V^T [b][kv][d][s]
__device__ float g_o  [(size_t)NTOK * HQ * HD];
__device__ float g_wfall[(size_t)BB * HQ * SS * SS];
__device__ float g_hst[(size_t)NTOK * DD];
__device__ float g_wqt[(size_t)HQ  * HD * DD];
__device__ float g_wkt[(size_t)HKV * HD * DD];
__device__ float g_wvt[(size_t)HKV * HD * DD];
__device__ float g_wot[(size_t)DD * HQ * HD];

// ---------------------------------------------------------------------------
__device__ __forceinline__ uint32_t f2tf32(float x) {
    uint32_t r; asm("cvt.rna.tf32.f32 %0, %1;" : "=r"(r) : "f"(x)); return r;
}
__device__ __forceinline__ float rtf(float x) { return __uint_as_float(f2tf32(x)); }
__device__ __forceinline__ void mma8(float* d, const uint32_t* a, const uint32_t* b) {
    asm volatile("mma.sync.aligned.m16n8k8.row.col.f32.tf32.tf32.f32 "
        "{%0,%1,%2,%3}, {%4,%5,%6,%7}, {%8,%9}, {%0,%1,%2,%3};"
        : "+f"(d[0]), "+f"(d[1]), "+f"(d[2]), "+f"(d[3])
        : "r"(a[0]), "r"(a[1]), "r"(a[2]), "r"(a[3]), "r"(b[0]), "r"(b[1]));
}

// 128x128 block tile, 256 threads (8 warps 2x4), warp tile 64x32, NT only.
// Inputs pre-rounded to tf32. Double-buffered k16 stages, fragment-ready
// STS.128 producers, 1 barrier per k16. 2 CTAs/SM -> 4 warps per SMSP.
template<int RND>
__device__ __forceinline__ void gemm_core(
    const float* __restrict__ A, const float* __restrict__ B,
    float* __restrict__ C, int lda, int ldb, int ldc,
    int kIters, float alpha)
{
    __shared__ uint32_t AsH[2][2][8][32][4];   // [stage][kt][mfrag][lane][reg]
    __shared__ uint32_t BsH[2][2][16][32][2];  // [stage][kt][nfrag][lane][reg]

    const int t = threadIdx.x;
    const int lane = t & 31;
    const int warp = t >> 5;
    const int wm = warp >> 2;   // 0..1
    const int wn = warp & 3;    // 0..3

    float acc[4][4][4];
#pragma unroll
    for (int i = 0; i < 4; i++)
#pragma unroll
        for (int j = 0; j < 4; j++)
#pragma unroll
            for (int r = 0; r < 4; r++) acc[i][j][r] = 0.f;

    // A producer (threads 0..127): pair p=t>>1 -> rows (mfA*16+gA, +8), ktA=t&1
    const bool aprod = (t < 128);
    const int pA = (t & 127) >> 1, ktA = t & 1;
    const int mfA = pA >> 3, gA = pA & 7;
    const float* ApA = A + (size_t)(mfA * 16 + gA) * lda + ktA * 8;
    const float* ApB = ApA + (size_t)8 * lda;
    // B producer (all 256): row n = t>>1, k half ktB = t&1
    const int nB = t >> 1, ktB = t & 1;
    const float* BpN = B + (size_t)nB * ldb + ktB * 8;
    const int nfB = nB >> 3, lbB = (nB & 7) * 4;

    float ax[16];    // rows (r, r+8), k 0..7 of ktA half
    float bz[8];     // row n, k 0..7 of ktB half
    {
        float4 v;
        if (aprod) {
            v = *(const float4*)(ApA);     ax[0]=v.x; ax[1]=v.y; ax[2]=v.z; ax[3]=v.w;
            v = *(const float4*)(ApA + 4); ax[4]=v.x; ax[5]=v.y; ax[6]=v.z; ax[7]=v.w;
            v = *(const float4*)(ApB);     ax[8]=v.x; ax[9]=v.y; ax[10]=v.z; ax[11]=v.w;
            v = *(const float4*)(ApB + 4); ax[12]=v.x; ax[13]=v.y; ax[14]=v.z; ax[15]=v.w;
        }
        v = *(const float4*)(BpN);     bz[0]=v.x; bz[1]=v.y; bz[2]=v.z; bz[3]=v.w;
        v = *(const float4*)(BpN + 4); bz[4]=v.x; bz[5]=v.y; bz[6]=v.z; bz[7]=v.w;
    }

    for (int it = 0; it < kIters; ++it) {
        const int st = it & 1;
        if (aprod) {
            uint4* dst = (uint4*)&AsH[st][ktA][mfA][gA * 4][0];
#pragma unroll
            for (int q = 0; q < 4; ++q)
                dst[q] = make_uint4(__float_as_uint(ax[q]),
                                    __float_as_uint(ax[8 + q]),
                                    __float_as_uint(ax[4 + q]),
                                    __float_as_uint(ax[12 + q]));
        }
        {
            uint4* dst = (uint4*)&BsH[st][ktB][nfB][lbB][0];
            dst[0] = make_uint4(__float_as_uint(bz[0]), __float_as_uint(bz[4]),
                                __float_as_uint(bz[1]), __float_as_uint(bz[5]));
            dst[1] = make_uint4(__float_as_uint(bz[2]), __float_as_uint(bz[6]),
                                __float_as_uint(bz[3]), __float_as_uint(bz[7]));
        }
        __syncthreads();
        // preload next iter
        if (it + 1 < kIters) {
            const int k0 = (it + 1) * 16;
            float4 v;
            if (aprod) {
                v = *(const float4*)(ApA + k0);     ax[0]=v.x; ax[1]=v.y; ax[2]=v.z; ax[3]=v.w;
                v = *(const float4*)(ApA + k0 + 4); ax[4]=v.x; ax[5]=v.y; ax[6]=v.z; ax[7]=v.w;
                v = *(const float4*)(ApB + k0);     ax[8]=v.x; ax[9]=v.y; ax[10]=v.z; ax[11]=v.w;
                v = *(const float4*)(ApB + k0 + 4); ax[12]=v.x; ax[13]=v.y; ax[14]=v.z; ax[15]=v.w;
            }
            v = *(const float4*)(BpN + k0);     bz[0]=v.x; bz[1]=v.y; bz[2]=v.z; bz[3]=v.w;
            v = *(const float4*)(BpN + k0 + 4); bz[4]=v.x; bz[5]=v.y; bz[6]=v.z; bz[7]=v.w;
        }
        // compute both k8 sub-tiles
#pragma unroll
        for (int kt = 0; kt < 2; kt++) {
            uint32_t ah[4][4];
#pragma unroll
            for (int i = 0; i < 4; i++) {
                uint4 h = *(const uint4*)&AsH[st][kt][wm * 4 + i][lane][0];
                ah[i][0] = h.x; ah[i][1] = h.y; ah[i][2] = h.z; ah[i][3] = h.w;
            }
            uint32_t bh[4][2];
#pragma unroll
            for (int j = 0; j < 4; j++) {
                uint2 h = *(const uint2*)&BsH[st][kt][wn * 4 + j][lane][0];
                bh[j][0] = h.x; bh[j][1] = h.y;
            }
#pragma unroll
            for (int i = 0; i < 4; i++)
#pragma unroll
                for (int j = 0; j < 4; j++)
                    mma8(acc[i][j], ah[i], bh[j]);
        }
    }
    const int g = lane >> 2, q = lane & 3;
#pragma unroll
    for (int i = 0; i < 4; i++) {
        int r0 = wm * 64 + i * 16 + g;
#pragma unroll
        for (int j = 0; j < 4; j++) {
            int col = wn * 32 + j * 8 + q * 2;
            float o0 = acc[i][j][0] * alpha, o1 = acc[i][j][1] * alpha;
            float o2 = acc[i][j][2] * alpha, o3 = acc[i][j][3] * alpha;
            if (RND) { o0 = rtf(o0); o1 = rtf(o1); o2 = rtf(o2); o3 = rtf(o3); }
            *(float2*)&C[(size_t)r0 * ldc + col]       = make_float2(o0, o1);
            *(float2*)&C[(size_t)(r0 + 8) * ldc + col] = make_float2(o2, o3);
        }
    }
}

// ---------------- wrappers -------------------------------------------------
__global__ void __launch_bounds__(256, 2) qkv_mma(
    const float* __restrict__ hs,
    const float* __restrict__ wq, const float* __restrict__ wk,
    const float* __restrict__ wv,
    float* __restrict__ qlin, float* __restrict__ klin, float* __restrict__ vlin)
{
    const int bx = blockIdx.x;
    int z, xb;
    if (bx < 16)      { z = 0; xb = bx; }
    else if (bx < 24) { z = 1; xb = bx - 16; }
    else              { z = 2; xb = bx - 24; }
    const int nblk = (z == 0) ? 16 : 8;
    const float* B = (z == 0) ? wq : ((z == 1) ? wk : wv);
    float* C       = (z == 0) ? qlin : ((z == 1) ? klin : vlin);
    const int ldc  = nblk * 128;
    gemm_core<0>(hs + (size_t)blockIdx.y * 128 * DD,
                 B  + (size_t)xb * 128 * DD,
                 C  + (size_t)blockIdx.y * 128 * ldc + xb * 128,
                 DD, DD, ldc, DD / 16, 1.f);
}

__global__ void __launch_bounds__(256, 2) wo_mma(
    const float* __restrict__ A, const float* __restrict__ B,
    float* __restrict__ C)
{
    gemm_core<0>(A + (size_t)blockIdx.y * 128 * (HQ * HD),
                 B + (size_t)blockIdx.x * 128 * (HQ * HD),
                 C + (size_t)blockIdx.y * 128 * DD + blockIdx.x * 128,
                 HQ * HD, HQ * HD, DD, (HQ * HD) / 16, 1.f);
}

// scores: compact triangular grid, 136 tiles per (b,h)
__global__ void __launch_bounds__(256, 2) scores_mma(
    const float* __restrict__ Q, const float* __restrict__ Kk,
    float* __restrict__ W)
{
    const int u = blockIdx.x, z = blockIdx.z;
    int by = (int)((sqrtf(8.f * (float)u + 1.f) - 1.f) * 0.5f);
    while ((by + 1) * (by + 2) / 2 <= u) by++;
    while (by * (by + 1) / 2 > u) by--;
    const int bx = u - by * (by + 1) / 2;
    const int kvz = (z >> 4) * HKV + ((z & 15) >> 1);
    gemm_core<0>(Q  + ((size_t)z   * SS + by * 128) * HD,
                 Kk + ((size_t)kvz * SS + bx * 128) * HD,
                 W + (size_t)z * SS * SS + (size_t)by * 128 * SS + bx * 128,
                 HD, HD, SS, HD / 16, 0.08838834764831845f);
}

// av: heaviest strips launch FIRST
__global__ void __launch_bounds__(256, 2) av_mma(
    const float* __restrict__ W, const float* __restrict__ Vt,
    float* __restrict__ O)
{
    const int by = 15 - blockIdx.y, z = blockIdx.z;
    const int kvz = (z >> 4) * HKV + ((z & 15) >> 1);
    gemm_core<1>(W  + (size_t)z * SS * SS + (size_t)by * 128 * SS,
                 Vt + (size_t)kvz * HD * SS,
                 O + (size_t)(z >> 4) * SS * (HQ * HD)
                   + (size_t)by * 128 * (HQ * HD) + (z & 15) * HD,
                 SS, SS, HQ * HD, (by + 1) * 8, 1.f);
}

// ============== tf32 pre-rounding ==========================================
__global__ void round_kernel(const float* __restrict__ src,
                             float* __restrict__ dst, int n4)
{
    int i = blockIdx.x * 256 + threadIdx.x;
    if (i >= n4) return;
    float4 v = ((const float4*)src)[i];
    v.x = rtf(v.x); v.y = rtf(v.y); v.z = rtf(v.z); v.w = rtf(v.w);
    ((float4*)dst)[i] = v;
}

// ======== RMSNorm + RoPE for Q/K. Grid (NTOK, 24), 128 threads =============
__global__ void rmsrope_kernel(const float* __restrict__ qlin,
                               const float* __restrict__ klin,
                               const float* __restrict__ cosb,
                               const float* __restrict__ sinb,
                               const float* __restrict__ qw,
                               const float* __restrict__ kw,
                               float* __restrict__ qout,
                               float* __restrict__ kout)
{
    const int token = blockIdx.x;
    const int y     = blockIdx.y;
    const int i     = threadIdx.x;
    const int b = token >> 11, s = token & (SS - 1);
    __shared__ float sh[128];
    __shared__ float red[4];

    float c  = cosb[(size_t)token * HD + i];
    float sn = sinb[(size_t)token * HD + i];
    float x, w;
    float* outp;
    if (y < HQ) {
        x = qlin[(size_t)token * (HQ * HD) + y * HD + i];
        w = qw[i];
        outp = qout + (((size_t)(b * HQ + y)) * SS + s) * HD;
    } else {
        int h = y - HQ;
        x = klin[(size_t)token * (HKV * HD) + h * HD + i];
        w = kw[i];
        outp = kout + (((size_t)(b * HKV + h)) * SS + s) * HD;
    }
    float ss = x * x;
#pragma unroll
    for (int off = 16; off; off >>= 1) ss += __shfl_xor_sync(0xffffffffu, ss, off);
    const int lane = i & 31, wd = i >> 5;
    if (lane == 0) red[wd] = ss;
    __syncthreads();
    ss = red[0] + red[1] + red[2] + red[3];
    float inv = rsqrtf(ss * (1.f / HD) + 1e-6f);
    float xn  = x * inv * w;
    sh[i] = xn;
    __syncthreads();
    float rot = (i < 64) ? -sh[i + 64] : sh[i - 64];
    outp[i] = rtf(xn * c + rot * sn);
}

// ======== V transpose: vlin [tok][kv*128] -> vt [b][kv][d][s] ==============
__global__ void vtrans_kernel(const float* __restrict__ vlin,
                              float* __restrict__ vt)
{
    __shared__ float tile[32][33];
    const int bkv = blockIdx.z;
    const int b = bkv >> 3, kv = bkv & 7;
    const int s0 = blockIdx.x * 32, d0 = blockIdx.y * 32;
    const int tx = threadIdx.x, ty = threadIdx.y;   // 32 x 8
#pragma unroll
    for (int r = 0; r < 32; r += 8) {
        int s = s0 + ty + r;
        tile[ty + r][tx] = vlin[((size_t)b * SS + s) * (HKV * HD) + kv * HD + d0 + tx];
    }
    __syncthreads();
#pragma unroll
    for (int r = 0; r < 32; r += 8) {
        int d = d0 + ty + r;
        vt[(((size_t)bkv) * HD + d) * SS + s0 + tx] = rtf(tile[tx][ty + r]);
    }
}

// ======= in-place causal softmax, float4 I/O, loads guarded by L ===========
__global__ void softmax_kernel(float* __restrict__ W)
{
    const size_t row = blockIdx.x;
    const int iq = (int)(row & (SS - 1));
    const int L = iq + 1;
    float4* p = (float4*)(W + row * SS);
    const int t = threadIdx.x;               // 256 threads, 2 f4 each
    __shared__ float red[8];

    float4 v[2];
#pragma unroll
    for (int r = 0; r < 2; ++r) {
        int e0 = (t + r * 256) * 4;
        v[r] = (e0 < L) ? p[t + r * 256] : make_float4(0.f, 0.f, 0.f, 0.f);
    }

    float m = -3.4e38f;
#pragma unroll
    for (int r = 0; r < 2; ++r) {
        int e0 = (t + r * 256) * 4;
        float* f = (float*)&v[r];
#pragma unroll
        for (int e = 0; e < 4; ++e) if (e0 + e < L) m = fmaxf(m, f[e]);
    }
#pragma unroll
    for (int off = 16; off; off >>= 1) m = fmaxf(m, __shfl_xor_sync(0xffffffffu, m, off));
    if ((t & 31) == 0) red[t >> 5] = m;
    __syncthreads();
    m = red[0];
#pragma unroll
    for (int wq = 1; wq < 8; wq++) m = fmaxf(m, red[wq]);
    __syncthreads();

    float ssum = 0.f;
#pragma unroll
    for (int r = 0; r < 2; ++r) {
        int e0 = (t + r * 256) * 4;
        float* f = (float*)&v[r];
#pragma unroll
        for (int e = 0; e < 4; ++e) {
            float ex = (e0 + e < L) ? __expf(f[e] - m) : 0.f;
            f[e] = ex;
            ssum += ex;
        }
    }
#pragma unroll
    for (int off = 16; off; off >>= 1) ssum += __shfl_xor_sync(0xffffffffu, ssum, off);
    if ((t & 31) == 0) red[t >> 5] = ssum;
    __syncthreads();
    ssum = red[0] + red[1] + red[2] + red[3] + red[4] + red[5] + red[6] + red[7];
    const float inv = 1.f / ssum;

#pragma unroll
    for (int r = 0; r < 2; ++r) {
        float* f = (float*)&v[r];
#pragma unroll
        for (int e = 0; e < 4; ++e) f[e] = rtf(f[e] * inv);
        p[t + r * 256] = v[r];
    }
}

// ============================== launch ======================================
extern "C" void kernel_launch(void* const* d_in, const int* in_sizes, int n_in,
                              void* d_out, int out_size)
{
    const float* hs   = (const float*)d_in[0];
    const float* cosb = (const float*)d_in[1];
    const float* sinb = (const float*)d_in[2];
    const float* Wq   = (const float*)d_in[4];
    const float* Wk   = (const float*)d_in[5];
    const float* Wv   = (const float*)d_in[6];
    const float* Wo   = (const float*)d_in[7];
    const float* qw   = (const float*)d_in[8];
    const float* kw   = (const float*)d_in[9];
    float* out = (float*)d_out;

    float *qlin, *klin, *vlin, *qr, *kr, *vt, *osc, *wfall;
    float *hst, *wqt, *wkt, *wvt, *wot;
    cudaGetSymbolAddress((void**)&qlin, g_qlin);
    cudaGetSymbolAddress((void**)&klin, g_klin);
    cudaGetSymbolAddress((void**)&vlin, g_vlin);
    cudaGetSymbolAddress((void**)&qr,   g_q);
    cudaGetSymbolAddress((void**)&kr,   g_k);
    cudaGetSymbolAddress((void**)&vt,   g_vt);
    cudaGetSymbolAddress((void**)&osc,  g_o);
    cudaGetSymbolAddress((void**)&wfall, g_wfall);
    cudaGetSymbolAddress((void**)&hst,  g_hst);
    cudaGetSymbolAddress((void**)&wqt,  g_wqt);
    cudaGetSymbolAddress((void**)&wkt,  g_wkt);
    cudaGetSymbolAddress((void**)&wvt,  g_wvt);
    cudaGetSymbolAddress((void**)&wot,  g_wot);

    const size_t OUT_ELEMS = (size_t)NTOK * DD;
    const size_t W_ELEMS   = (size_t)BB * HQ * SS * SS;
    float* wptr = ((size_t)out_size >= OUT_ELEMS + W_ELEMS) ? (out + OUT_ELEMS)
                                                            : wfall;

    // tf32 pre-rounding of raw GEMM inputs
    {
        int n;
        n = NTOK * DD / 4;        round_kernel<<<(n + 255) / 256, 256>>>(hs, hst, n);
        n = HQ * HD * DD / 4;     round_kernel<<<(n + 255) / 256, 256>>>(Wq, wqt, n);
        n = HKV * HD * DD / 4;    round_kernel<<<(n + 255) / 256, 256>>>(Wk, wkt, n);
        n = HKV * HD * DD / 4;    round_kernel<<<(n + 255) / 256, 256>>>(Wv, wvt, n);
        n = DD * HQ * HD / 4;     round_kernel<<<(n + 255) / 256, 256>>>(Wo, wot, n);
    }

    dim3 blk(256);
    // QKV projections (compact grid)
    qkv_mma<<<dim3(32, NTOK / 128), blk>>>(hst, wqt, wkt, wvt, qlin, klin, vlin);
    // RMSNorm + RoPE (Q,K)
    rmsrope_kernel<<<dim3(NTOK, HQ + HKV), 128>>>(qlin, klin, cosb, sinb,
                                                  qw, kw, qr, kr);
    // V transpose
    vtrans_kernel<<<dim3(SS / 32, HD / 32, BB * HKV), dim3(32, 8)>>>(vlin, vt);
    // scores (compact triangular grid)
    scores_mma<<<dim3(136, 1, NBH), blk>>>(qr, kr, wptr);
    // in-place causal softmax
    softmax_kernel<<<(unsigned)(NBH * SS), 256>>>(wptr);
    // AV (causal K bound, heavy-first)
    av_mma<<<dim3(1, SS / 128, NBH), blk>>>(wptr, vt, osc);
    // output projection
    wo_mma<<<dim3(DD / 128, NTOK / 128), blk>>>(osc, wot, out);
}

// round 17
// speedup vs baseline: 1.1440x; 1.0154x over previous
#include <cuda_runtime.h>
#include <cstdint>

#define BB   2
#define SS   2048
#define DD   1024
#define HQ   16
#define HKV  8
#define HD   128
#define NTOK (BB*SS)
#define NBH  (BB*HQ)

// ---------------- device scratch ------------------------------------------
__device__ float g_qlin[(size_t)NTOK * HQ  * HD];
__device__ float g_klin[(size_t)NTOK * HKV * HD];
__device__ float g_vlin[(size_t)NTOK * HKV * HD];
__device__ float g_q  [(size_t)BB * HQ  * SS * HD];
__device__ float g_k  [(size_t)BB * HKV * SS * HD];
__device__ float g_vt [(size_t)BB * HKV * HD * SS];   // V^T [b][kv][d][s]
__device__ float g_o  [(size_t)NTOK * HQ * HD];
__device__ float g_wfall[(size_t)BB * HQ * SS * SS];

// ---------------------------------------------------------------------------
__device__ __forceinline__ uint32_t f2tf32(float x) {
    uint32_t r; asm("cvt.rna.tf32.f32 %0, %1;" : "=r"(r) : "f"(x)); return r;
}
__device__ __forceinline__ float rtf(float x) { return __uint_as_float(f2tf32(x)); }
__device__ __forceinline__ void mma8(float* d, const uint32_t* a, const uint32_t* b) {
    asm volatile("mma.sync.aligned.m16n8k8.row.col.f32.tf32.tf32.f32 "
        "{%0,%1,%2,%3}, {%4,%5,%6,%7}, {%8,%9}, {%0,%1,%2,%3};"
        : "+f"(d[0]), "+f"(d[1]), "+f"(d[2]), "+f"(d[3])
        : "r"(a[0]), "r"(a[1]), "r"(a[2]), "r"(a[3]), "r"(b[0]), "r"(b[1]));
}

// 128x128 block tile, 256 threads (8 warps 2x4), warp tile 64x32, NT only.
// Producers round to tf32 at STS-pack time (raw fp32 inputs OK).
// Double-buffered k16 stages, fragment-ready STS.128 producers,
// 1 barrier per k16. 2 CTAs/SM -> 4 warps per SMSP.
template<int RND>
__device__ __forceinline__ void gemm_core(
    const float* __restrict__ A, const float* __restrict__ B,
    float* __restrict__ C, int lda, int ldb, int ldc,
    int kIters, float alpha)
{
    __shared__ uint32_t AsH[2][2][8][32][4];   // [stage][kt][mfrag][lane][reg]
    __shared__ uint32_t BsH[2][2][16][32][2];  // [stage][kt][nfrag][lane][reg]

    const int t = threadIdx.x;
    const int lane = t & 31;
    const int warp = t >> 5;
    const int wm = warp >> 2;   // 0..1
    const int wn = warp & 3;    // 0..3

    float acc[4][4][4];
#pragma unroll
    for (int i = 0; i < 4; i++)
#pragma unroll
        for (int j = 0; j < 4; j++)
#pragma unroll
            for (int r = 0; r < 4; r++) acc[i][j][r] = 0.f;

    // A producer (threads 0..127): pair p=t>>1 -> rows (mfA*16+gA, +8), ktA=t&1
    const bool aprod = (t < 128);
    const int pA = (t & 127) >> 1, ktA = t & 1;
    const int mfA = pA >> 3, gA = pA & 7;
    const float* ApA = A + (size_t)(mfA * 16 + gA) * lda + ktA * 8;
    const float* ApB = ApA + (size_t)8 * lda;
    // B producer (all 256): row n = t>>1, k half ktB = t&1
    const int nB = t >> 1, ktB = t & 1;
    const float* BpN = B + (size_t)nB * ldb + ktB * 8;
    const int nfB = nB >> 3, lbB = (nB & 7) * 4;

    float ax[16];    // rows (r, r+8), k 0..7 of ktA half
    float bz[8];     // row n, k 0..7 of ktB half
    {
        float4 v;
        if (aprod) {
            v = *(const float4*)(ApA);     ax[0]=v.x; ax[1]=v.y; ax[2]=v.z; ax[3]=v.w;
            v = *(const float4*)(ApA + 4); ax[4]=v.x; ax[5]=v.y; ax[6]=v.z; ax[7]=v.w;
            v = *(const float4*)(ApB);     ax[8]=v.x; ax[9]=v.y; ax[10]=v.z; ax[11]=v.w;
            v = *(const float4*)(ApB + 4); ax[12]=v.x; ax[13]=v.y; ax[14]=v.z; ax[15]=v.w;
        }
        v = *(const float4*)(BpN);     bz[0]=v.x; bz[1]=v.y; bz[2]=v.z; bz[3]=v.w;
        v = *(const float4*)(BpN + 4); bz[4]=v.x; bz[5]=v.y; bz[6]=v.z; bz[7]=v.w;
    }

    for (int it = 0; it < kIters; ++it) {
        const int st = it & 1;
        if (aprod) {
            uint4* dst = (uint4*)&AsH[st][ktA][mfA][gA * 4][0];
#pragma unroll
            for (int q = 0; q < 4; ++q)
                dst[q] = make_uint4(f2tf32(ax[q]),
                                    f2tf32(ax[8 + q]),
                                    f2tf32(ax[4 + q]),
                                    f2tf32(ax[12 + q]));
        }
        {
            uint4* dst = (uint4*)&BsH[st][ktB][nfB][lbB][0];
            dst[0] = make_uint4(f2tf32(bz[0]), f2tf32(bz[4]),
                                f2tf32(bz[1]), f2tf32(bz[5]));
            dst[1] = make_uint4(f2tf32(bz[2]), f2tf32(bz[6]),
                                f2tf32(bz[3]), f2tf32(bz[7]));
        }
        __syncthreads();
        // preload next iter
        if (it + 1 < kIters) {
            const int k0 = (it + 1) * 16;
            float4 v;
            if (aprod) {
                v = *(const float4*)(ApA + k0);     ax[0]=v.x; ax[1]=v.y; ax[2]=v.z; ax[3]=v.w;
                v = *(const float4*)(ApA + k0 + 4); ax[4]=v.x; ax[5]=v.y; ax[6]=v.z; ax[7]=v.w;
                v = *(const float4*)(ApB + k0);     ax[8]=v.x; ax[9]=v.y; ax[10]=v.z; ax[11]=v.w;
                v = *(const float4*)(ApB + k0 + 4); ax[12]=v.x; ax[13]=v.y; ax[14]=v.z; ax[15]=v.w;
            }
            v = *(const float4*)(BpN + k0);     bz[0]=v.x; bz[1]=v.y; bz[2]=v.z; bz[3]=v.w;
            v = *(const float4*)(BpN + k0 + 4); bz[4]=v.x; bz[5]=v.y; bz[6]=v.z; bz[7]=v.w;
        }
        // compute both k8 sub-tiles
#pragma unroll
        for (int kt = 0; kt < 2; kt++) {
            uint32_t ah[4][4];
#pragma unroll
            for (int i = 0; i < 4; i++) {
                uint4 h = *(const uint4*)&AsH[st][kt][wm * 4 + i][lane][0];
                ah[i][0] = h.x; ah[i][1] = h.y; ah[i][2] = h.z; ah[i][3] = h.w;
            }
            uint32_t bh[4][2];
#pragma unroll
            for (int j = 0; j < 4; j++) {
                uint2 h = *(const uint2*)&BsH[st][kt][wn * 4 + j][lane][0];
                bh[j][0] = h.x; bh[j][1] = h.y;
            }
#pragma unroll
            for (int i = 0; i < 4; i++)
#pragma unroll
                for (int j = 0; j < 4; j++)
                    mma8(acc[i][j], ah[i], bh[j]);
        }
    }
    const int g = lane >> 2, q = lane & 3;
#pragma unroll
    for (int i = 0; i < 4; i++) {
        int r0 = wm * 64 + i * 16 + g;
#pragma unroll
        for (int j = 0; j < 4; j++) {
            int col = wn * 32 + j * 8 + q * 2;
            float o0 = acc[i][j][0] * alpha, o1 = acc[i][j][1] * alpha;
            float o2 = acc[i][j][2] * alpha, o3 = acc[i][j][3] * alpha;
            if (RND) { o0 = rtf(o0); o1 = rtf(o1); o2 = rtf(o2); o3 = rtf(o3); }
            *(float2*)&C[(size_t)r0 * ldc + col]       = make_float2(o0, o1);
            *(float2*)&C[(size_t)(r0 + 8) * ldc + col] = make_float2(o2, o3);
        }
    }
}

// ---------------- wrappers -------------------------------------------------
__global__ void __launch_bounds__(256, 2) qkv_mma(
    const float* __restrict__ hs,
    const float* __restrict__ wq, const float* __restrict__ wk,
    const float* __restrict__ wv,
    float* __restrict__ qlin, float* __restrict__ klin, float* __restrict__ vlin)
{
    const int bx = blockIdx.x;
    int z, xb;
    if (bx < 16)      { z = 0; xb = bx; }
    else if (bx < 24) { z = 1; xb = bx - 16; }
    else              { z = 2; xb = bx - 24; }
    const int nblk = (z == 0) ? 16 : 8;
    const float* B = (z == 0) ? wq : ((z == 1) ? wk : wv);
    float* C       = (z == 0) ? qlin : ((z == 1) ? klin : vlin);
    const int ldc  = nblk * 128;
    gemm_core<0>(hs + (size_t)blockIdx.y * 128 * DD,
                 B  + (size_t)xb * 128 * DD,
                 C  + (size_t)blockIdx.y * 128 * ldc + xb * 128,
                 DD, DD, ldc, DD / 16, 1.f);
}

__global__ void __launch_bounds__(256, 2) wo_mma(
    const float* __restrict__ A, const float* __restrict__ B,
    float* __restrict__ C)
{
    gemm_core<0>(A + (size_t)blockIdx.y * 128 * (HQ * HD),
                 B + (size_t)blockIdx.x * 128 * (HQ * HD),
                 C + (size_t)blockIdx.y * 128 * DD + blockIdx.x * 128,
                 HQ * HD, HQ * HD, DD, (HQ * HD) / 16, 1.f);
}

// scores: compact triangular grid, 136 tiles per (b,h)
__global__ void __launch_bounds__(256, 2) scores_mma(
    const float* __restrict__ Q, const float* __restrict__ Kk,
    float* __restrict__ W)
{
    const int u = blockIdx.x, z = blockIdx.z;
    int by = (int)((sqrtf(8.f * (float)u + 1.f) - 1.f) * 0.5f);
    while ((by + 1) * (by + 2) / 2 <= u) by++;
    while (by * (by + 1) / 2 > u) by--;
    const int bx = u - by * (by + 1) / 2;
    const int kvz = (z >> 4) * HKV + ((z & 15) >> 1);
    gemm_core<0>(Q  + ((size_t)z   * SS + by * 128) * HD,
                 Kk + ((size_t)kvz * SS + bx * 128) * HD,
                 W + (size_t)z * SS * SS + (size_t)by * 128 * SS + bx * 128,
                 HD, HD, SS, HD / 16, 0.08838834764831845f);
}

// av: heaviest strips launch FIRST
__global__ void __launch_bounds__(256, 2) av_mma(
    const float* __restrict__ W, const float* __restrict__ Vt,
    float* __restrict__ O)
{
    const int by = 15 - blockIdx.y, z = blockIdx.z;
    const int kvz = (z >> 4) * HKV + ((z & 15) >> 1);
    gemm_core<1>(W  + (size_t)z * SS * SS + (size_t)by * 128 * SS,
                 Vt + (size_t)kvz * HD * SS,
                 O + (size_t)(z >> 4) * SS * (HQ * HD)
                   + (size_t)by * 128 * (HQ * HD) + (z & 15) * HD,
                 SS, SS, HQ * HD, (by + 1) * 8, 1.f);
}

// ======== RMSNorm + RoPE for Q/K. Grid (NTOK, 24), 128 threads =============
__global__ void rmsrope_kernel(const float* __restrict__ qlin,
                               const float* __restrict__ klin,
                               const float* __restrict__ cosb,
                               const float* __restrict__ sinb,
                               const float* __restrict__ qw,
                               const float* __restrict__ kw,
                               float* __restrict__ qout,
                               float* __restrict__ kout)
{
    const int token = blockIdx.x;
    const int y     = blockIdx.y;
    const int i     = threadIdx.x;
    const int b = token >> 11, s = token & (SS - 1);
    __shared__ float sh[128];
    __shared__ float red[4];

    float c  = cosb[(size_t)token * HD + i];
    float sn = sinb[(size_t)token * HD + i];
    float x, w;
    float* outp;
    if (y < HQ) {
        x = qlin[(size_t)token * (HQ * HD) + y * HD + i];
        w = qw[i];
        outp = qout + (((size_t)(b * HQ + y)) * SS + s) * HD;
    } else {
        int h = y - HQ;
        x = klin[(size_t)token * (HKV * HD) + h * HD + i];
        w = kw[i];
        outp = kout + (((size_t)(b * HKV + h)) * SS + s) * HD;
    }
    float ss = x * x;
#pragma unroll
    for (int off = 16; off; off >>= 1) ss += __shfl_xor_sync(0xffffffffu, ss, off);
    const int lane = i & 31, wd = i >> 5;
    if (lane == 0) red[wd] = ss;
    __syncthreads();
    ss = red[0] + red[1] + red[2] + red[3];
    float inv = rsqrtf(ss * (1.f / HD) + 1e-6f);
    float xn  = x * inv * w;
    sh[i] = xn;
    __syncthreads();
    float rot = (i < 64) ? -sh[i + 64] : sh[i - 64];
    outp[i] = rtf(xn * c + rot * sn);
}

// ======== V transpose: vlin [tok][kv*128] -> vt [b][kv][d][s] ==============
__global__ void vtrans_kernel(const float* __restrict__ vlin,
                              float* __restrict__ vt)
{
    __shared__ float tile[32][33];
    const int bkv = blockIdx.z;
    const int b = bkv >> 3, kv = bkv & 7;
    const int s0 = blockIdx.x * 32, d0 = blockIdx.y * 32;
    const int tx = threadIdx.x, ty = threadIdx.y;   // 32 x 8
#pragma unroll
    for (int r = 0; r < 32; r += 8) {
        int s = s0 + ty + r;
        tile[ty + r][tx] = vlin[((size_t)b * SS + s) * (HKV * HD) + kv * HD + d0 + tx];
    }
    __syncthreads();
#pragma unroll
    for (int r = 0; r < 32; r += 8) {
        int d = d0 + ty + r;
        vt[(((size_t)bkv) * HD + d) * SS + s0 + tx] = rtf(tile[tx][ty + r]);
    }
}

// ======= in-place causal softmax, float4 I/O, loads guarded by L ===========
__global__ void softmax_kernel(float* __restrict__ W)
{
    const size_t row = blockIdx.x;
    const int iq = (int)(row & (SS - 1));
    const int L = iq + 1;
    float4* p = (float4*)(W + row * SS);
    const int t = threadIdx.x;               // 256 threads, 2 f4 each
    __shared__ float red[8];

    float4 v[2];
#pragma unroll
    for (int r = 0; r < 2; ++r) {
        int e0 = (t + r * 256) * 4;
        v[r] = (e0 < L) ? p[t + r * 256] : make_float4(0.f, 0.f, 0.f, 0.f);
    }

    float m = -3.4e38f;
#pragma unroll
    for (int r = 0; r < 2; ++r) {
        int e0 = (t + r * 256) * 4;
        float* f = (float*)&v[r];
#pragma unroll
        for (int e = 0; e < 4; ++e) if (e0 + e < L) m = fmaxf(m, f[e]);
    }
#pragma unroll
    for (int off = 16; off; off >>= 1) m = fmaxf(m, __shfl_xor_sync(0xffffffffu, m, off));
    if ((t & 31) == 0) red[t >> 5] = m;
    __syncthreads();
    m = red[0];
#pragma unroll
    for (int wq = 1; wq < 8; wq++) m = fmaxf(m, red[wq]);
    __syncthreads();

    float ssum = 0.f;
#pragma unroll
    for (int r = 0; r < 2; ++r) {
        int e0 = (t + r * 256) * 4;
        float* f = (float*)&v[r];
#pragma unroll
        for (int e = 0; e < 4; ++e) {
            float ex = (e0 + e < L) ? __expf(f[e] - m) : 0.f;
            f[e] = ex;
            ssum += ex;
        }
    }
#pragma unroll
    for (int off = 16; off; off >>= 1) ssum += __shfl_xor_sync(0xffffffffu, ssum, off);
    if ((t & 31) == 0) red[t >> 5] = ssum;
    __syncthreads();
    ssum = red[0] + red[1] + red[2] + red[3] + red[4] + red[5] + red[6] + red[7];
    const float inv = 1.f / ssum;

#pragma unroll
    for (int r = 0; r < 2; ++r) {
        float* f = (float*)&v[r];
#pragma unroll
        for (int e = 0; e < 4; ++e) f[e] = rtf(f[e] * inv);
        p[t + r * 256] = v[r];
    }
}

// ============================== launch ======================================
extern "C" void kernel_launch(void* const* d_in, const int* in_sizes, int n_in,
                              void* d_out, int out_size)
{
    const float* hs   = (const float*)d_in[0];
    const float* cosb = (const float*)d_in[1];
    const float* sinb = (const float*)d_in[2];
    const float* Wq   = (const float*)d_in[4];
    const float* Wk   = (const float*)d_in[5];
    const float* Wv   = (const float*)d_in[6];
    const float* Wo   = (const float*)d_in[7];
    const float* qw   = (const float*)d_in[8];
    const float* kw   = (const float*)d_in[9];
    float* out = (float*)d_out;

    float *qlin, *klin, *vlin, *qr, *kr, *vt, *osc, *wfall;
    cudaGetSymbolAddress((void**)&qlin, g_qlin);
    cudaGetSymbolAddress((void**)&klin, g_klin);
    cudaGetSymbolAddress((void**)&vlin, g_vlin);
    cudaGetSymbolAddress((void**)&qr,   g_q);
    cudaGetSymbolAddress((void**)&kr,   g_k);
    cudaGetSymbolAddress((void**)&vt,   g_vt);
    cudaGetSymbolAddress((void**)&osc,  g_o);
    cudaGetSymbolAddress((void**)&wfall, g_wfall);

    const size_t OUT_ELEMS = (size_t)NTOK * DD;
    const size_t W_ELEMS   = (size_t)BB * HQ * SS * SS;
    float* wptr = ((size_t)out_size >= OUT_ELEMS + W_ELEMS) ? (out + OUT_ELEMS)
                                                            : wfall;

    dim3 blk(256);
    // QKV projections (raw inputs; producers round to tf32)
    qkv_mma<<<dim3(32, NTOK / 128), blk>>>(hs, Wq, Wk, Wv, qlin, klin, vlin);
    // RMSNorm + RoPE (Q,K)
    rmsrope_kernel<<<dim3(NTOK, HQ + HKV), 128>>>(qlin, klin, cosb, sinb,
                                                  qw, kw, qr, kr);
    // V transpose
    vtrans_kernel<<<dim3(SS / 32, HD / 32, BB * HKV), dim3(32, 8)>>>(vlin, vt);
    // scores (compact triangular grid)
    scores_mma<<<dim3(136, 1, NBH), blk>>>(qr, kr, wptr);
    // in-place causal softmax
    softmax_kernel<<<(unsigned)(NBH * SS), 256>>>(wptr);
    // AV (causal K bound, heavy-first)
    av_mma<<<dim3(1, SS / 128, NBH), blk>>>(wptr, vt, osc);
    // output projection
    wo_mma<<<dim3(DD / 128, NTOK / 128), blk>>>(osc, Wo, out);
}